// round 5
// baseline (speedup 1.0000x reference)
#include <cuda_runtime.h>
#include <math.h>
#include <float.h>

#define XS 2048
#define NN 4096
#define ZS 64
#define DD 6208
#define NV4 1552          // DD/4
#define TK 16
#define ZTK 8
#define EPSF 1e-9f
#define RNDF 0.5f
#define NCHUNK 64         // 32 rows per chunk
#define MIXBLK 128        // NCHUNK * 2 column-halves
#define HALF4 776         // NV4/2

// ---------------- device scratch (no allocations allowed) ----------------
__device__ __align__(16) float g_inpt[DD];
__device__ float g_w[DD];                 // (ages-1)/ages
__device__ __align__(16) float g_resp[DD];
__device__ __align__(16) float g_mix_x[DD];
__device__ __align__(16) float g_mix_y[DD];
__device__ __align__(16) float g_mix_z[DD];
__device__ float4 g_part4[NCHUNK][NV4];   // deterministic partial sums
__device__ float g_cval[32][TK + 1];      // per-warp sorted y candidates
__device__ int   g_crow[32][TK + 1];
__device__ float g_yval[TK + 1];
__device__ int   g_yrow[TK + 1];
__device__ float g_zval[ZTK + 1];
__device__ int   g_zrow[ZTK + 1];
__device__ float g_inv_dx;

// ---------------- helpers ----------------
__device__ __forceinline__ float blockReduceSumB(float v) {
    __shared__ float red[8];
    __shared__ float bcast;
    int lane = threadIdx.x & 31;
    int wid  = threadIdx.x >> 5;
#pragma unroll
    for (int o = 16; o > 0; o >>= 1) v += __shfl_down_sync(0xffffffffu, v, o);
    if (lane == 0) red[wid] = v;
    __syncthreads();
    if (wid == 0) {
        float x = (lane < 8) ? red[lane] : 0.0f;
#pragma unroll
        for (int o = 4; o > 0; o >>= 1) x += __shfl_down_sync(0xffffffffu, x, o);
        if (lane == 0) bcast = x;
    }
    __syncthreads();
    return bcast;
}

__device__ __forceinline__ void warpArgMax(float& bv, int& bi) {
#pragma unroll
    for (int o = 16; o > 0; o >>= 1) {
        float ov = __shfl_down_sync(0xffffffffu, bv, o);
        int   oi = __shfl_down_sync(0xffffffffu, bi, o);
        if (ov > bv || (ov == bv && oi < bi)) { bv = ov; bi = oi; }
    }
}

// ---------------- K1: build inpt, weights, zero final, copy ages ----------------
__global__ void k_init(const float* __restrict__ x, const float* __restrict__ z,
                       const float* __restrict__ yresp, const float* __restrict__ ages,
                       float* __restrict__ out_z, float* __restrict__ out_final,
                       float* __restrict__ out_ages) {
    int i = blockIdx.x * 256 + threadIdx.x;
    if (i < DD) {
        float v;
        if (i < XS)           v = x[i];
        else if (i < XS + NN) v = yresp[i - XS];
        else                  v = z[i - XS - NN];
        g_inpt[i] = v;
        float a = ages[i];
        g_w[i] = (a - 1.0f) / a;
        out_final[i] = 0.0f;
        out_ages[i]  = a;
    }
    if (i < ZS) out_z[i] = 0.0f;
}

// ---------------- K2: fused mixx (blocks 0..127) + matvec/copy (blocks 128..) ----------------
__global__ void k_main(const float4* __restrict__ neu4, float* __restrict__ out_neu) {
    int t = threadIdx.x;
    int b = blockIdx.x;

    if (b < MIXBLK) {
        // ---- mix_x partials: chunk of 32 rows, one column half, float4 ----
        int chunk = b >> 1;
        int half  = b & 1;
        int r0 = chunk * 32;
        int r1 = min(r0 + 32, XS - 1);
        int cbase = half * HALF4;
        float4 acc0 = {0,0,0,0}, acc1 = {0,0,0,0}, acc2 = {0,0,0,0}, acc3 = {0,0,0,0};
        int c0 = cbase + t;
        int c1 = cbase + 256 + t;
        int c2 = cbase + 512 + t;
        int c3 = cbase + 768 + t;          // valid only for t < 8
        bool v3 = (768 + t) < HALF4;
        for (int r = r0; r < r1; r++) {
            float w = g_w[r];
            const float4* rowp = neu4 + (size_t)r * NV4;
            float4 a = __ldg(rowp + c0);
            float4 bq = __ldg(rowp + c1);
            float4 cq = __ldg(rowp + c2);
            float4 dq = v3 ? __ldg(rowp + c3) : make_float4(0,0,0,0);
            acc0.x = fmaf(w, a.x, acc0.x);  acc0.y = fmaf(w, a.y, acc0.y);
            acc0.z = fmaf(w, a.z, acc0.z);  acc0.w = fmaf(w, a.w, acc0.w);
            acc1.x = fmaf(w, bq.x, acc1.x); acc1.y = fmaf(w, bq.y, acc1.y);
            acc1.z = fmaf(w, bq.z, acc1.z); acc1.w = fmaf(w, bq.w, acc1.w);
            acc2.x = fmaf(w, cq.x, acc2.x); acc2.y = fmaf(w, cq.y, acc2.y);
            acc2.z = fmaf(w, cq.z, acc2.z); acc2.w = fmaf(w, cq.w, acc2.w);
            acc3.x = fmaf(w, dq.x, acc3.x); acc3.y = fmaf(w, dq.y, acc3.y);
            acc3.z = fmaf(w, dq.z, acc3.z); acc3.w = fmaf(w, dq.w, acc3.w);
        }
        g_part4[chunk][c0] = acc0;
        g_part4[chunk][c1] = acc1;
        g_part4[chunk][c2] = acc2;
        if (v3) g_part4[chunk][c3] = acc3;
        return;
    }

    // ---- matvec row + fused copy (skip rows < XS-1, rewritten later) ----
    int row = b - MIXBLK;
    const float4* src = neu4 + (size_t)row * NV4;
    float4* dst = reinterpret_cast<float4*>(out_neu) + (size_t)row * NV4;
    const float4* ip = reinterpret_cast<const float4*>(g_inpt);
    float acc = 0.0f;
    bool docopy = (row >= XS - 1);
#pragma unroll
    for (int j = 0; j < 7; j++) {
        int c = t + j * 256;
        if (c < NV4) {
            float4 v = __ldg(src + c);
            float4 w = ip[c];
            acc = fmaf(v.x, w.x, acc);
            acc = fmaf(v.y, w.y, acc);
            acc = fmaf(v.z, w.z, acc);
            acc = fmaf(v.w, w.w, acc);
            if (docopy) __stcs(dst + c, v);
        }
    }
    float tot = blockReduceSumB(acc);
    if (t == 0) g_resp[row] = tot;
}

// ---------------- K4a: per-warp sorted y top-17 (32 blocks x 1 warp) ----------------
__global__ void k_ycand() {
    int w    = blockIdx.x;       // 0..31
    int lane = threadIdx.x;      // 0..31
    int gbase = XS + w * 128 + lane * 4;
    float4 vy = *(const float4*)&g_resp[gbase];
    float v[4] = {vy.x, vy.y, vy.z, vy.w};
    int baseL = lane * 4;
#pragma unroll 1
    for (int k = 0; k < TK + 1; k++) {
        float bv = v[0]; int bi = baseL;
#pragma unroll
        for (int j = 1; j < 4; j++)
            if (v[j] > bv) { bv = v[j]; bi = baseL + j; }   // strict > keeps lowest idx
        warpArgMax(bv, bi);
        bv = __shfl_sync(0xffffffffu, bv, 0);
        bi = __shfl_sync(0xffffffffu, bi, 0);
        if (lane == 0) { g_cval[w][k] = bv; g_crow[w][k] = XS + w * 128 + bi; }
        if ((bi >> 2) == lane) v[bi & 3] = -FLT_MAX;
    }
}

// ---------------- K4b: merge + z top-9 + x max + all scalar finals ----------------
__global__ void k_final(const float* __restrict__ ages, float* __restrict__ out_z,
                        float* __restrict__ out_final, float* __restrict__ out_ages) {
    __shared__ float s_cv[32][TK + 1];
    __shared__ int   s_ci[32][TK + 1];
    __shared__ float s_xv[32];
    __shared__ int   s_xnz[32];
    __shared__ float s_yv[TK + 1];
    __shared__ int   s_yr[TK + 1];
    __shared__ float s_zv[ZTK + 1];
    __shared__ int   s_zr[ZTK + 1];
    __shared__ float s_invdx;

    int t    = threadIdx.x;       // 0..1023
    int lane = t & 31;
    int wid  = t >> 5;

    if (t < 32 * (TK + 1)) {
        ((float*)s_cv)[t] = ((const float*)g_cval)[t];
        ((int*)s_ci)[t]   = ((const int*)g_crow)[t];
    }

    float xa = g_resp[t], xb = g_resp[t + 1024];
    {
        float bv = fmaxf(xa, xb);
        int   nz = (xa != 0.0f) | (xb != 0.0f);
#pragma unroll
        for (int o = 16; o > 0; o >>= 1) {
            bv  = fmaxf(bv, __shfl_down_sync(0xffffffffu, bv, o));
            nz |= __shfl_down_sync(0xffffffffu, nz, o);
        }
        if (lane == 0) { s_xv[wid] = bv; s_xnz[wid] = nz; }
    }
    __syncthreads();

    if (wid == 0) {
        int p = 0;
        float hv = s_cv[lane][0];
        int   hi = s_ci[lane][0];
#pragma unroll 1
        for (int k = 0; k < TK + 1; k++) {
            float bv = hv; int bi = hi;
            warpArgMax(bv, bi);
            bv = __shfl_sync(0xffffffffu, bv, 0);
            bi = __shfl_sync(0xffffffffu, bi, 0);
            if (lane == 0) { s_yv[k] = bv; s_yr[k] = bi; g_yval[k] = bv; g_yrow[k] = bi; }
            if (hi == bi) {
                p++;
                if (p < TK + 1) { hv = s_cv[lane][p]; hi = s_ci[lane][p]; }
                else            { hv = -FLT_MAX; hi = 1 << 30; }
            }
        }
    } else if (wid == 1) {
        float z0 = g_resp[XS + NN + lane];
        float z1 = g_resp[XS + NN + 32 + lane];
#pragma unroll 1
        for (int k = 0; k < ZTK + 1; k++) {
            float bv = z0; int bi = lane;
            if (z1 > bv) { bv = z1; bi = lane + 32; }
            warpArgMax(bv, bi);
            bv = __shfl_sync(0xffffffffu, bv, 0);
            bi = __shfl_sync(0xffffffffu, bi, 0);
            if (lane == 0) { s_zv[k] = bv; s_zr[k] = XS + NN + bi;
                             g_zval[k] = bv; g_zrow[k] = XS + NN + bi; }
            if (bi == lane)      z0 = -FLT_MAX;
            if (bi == lane + 32) z1 = -FLT_MAX;
        }
    } else if (wid == 2) {
        float bv = s_xv[lane]; int nz = s_xnz[lane];
#pragma unroll
        for (int o = 16; o > 0; o >>= 1) {
            bv  = fmaxf(bv, __shfl_down_sync(0xffffffffu, bv, o));
            nz |= __shfl_down_sync(0xffffffffu, nz, o);
        }
        if (lane == 0) {
            float tx = nz ? 0.0f : 1.0f;
            float inv = 1.0f / (bv + EPSF * tx * RNDF);
            s_invdx = inv;
            g_inv_dx = inv;
        }
    }
    __syncthreads();

    if (t == 0) {
        float yvL = s_yv[TK];
        float ty = 0.0f;
#pragma unroll
        for (int k = 0; k < TK; k++) if (s_yv[k] == yvL) ty = 1.0f;
        float dy = 1.0f / (s_yv[0] - yvL + EPSF * ty * RNDF);
#pragma unroll
        for (int k = 0; k < TK; k++) {
            int r = s_yr[k];
            out_final[r] = (s_yv[k] - yvL) * dy;
            out_ages[r]  = ages[r] + 1.0f;
        }
        float zvL = s_zv[ZTK];
        float dz = 1.0f / (s_zv[0] - zvL);
#pragma unroll
        for (int k = 0; k < ZTK; k++) {
            int r = s_zr[k];
            float f = (s_zv[k] - zvL) * dz;
            out_final[r] = f;
            out_z[r - (XS + NN)] = f;
            out_ages[r] = ages[r] + 1.0f;
        }
    }

    float inv = s_invdx;
    out_final[t]        = xa * inv;
    out_final[t + 1024] = xb * inv;
    out_ages[t] = ages[t] + 1.0f;                      // t <= 1023 < XS-1
    if (t + 1024 < XS - 1) out_ages[t + 1024] = ages[t + 1024] + 1.0f;
}

// ---------------- K6: reduce mix_x partials; compute mix_y, mix_z (float4) ----------------
__global__ void k_mixyz(const float4* __restrict__ neu4) {
    int c4 = blockIdx.x * 256 + threadIdx.x;
    if (c4 >= NV4) return;
    float4 mx = {0,0,0,0};
#pragma unroll
    for (int ch = 0; ch < NCHUNK; ch++) {
        float4 p = g_part4[ch][c4];
        mx.x += p.x; mx.y += p.y; mx.z += p.z; mx.w += p.w;
    }
    reinterpret_cast<float4*>(g_mix_x)[c4] = mx;

    float4 my = {0,0,0,0};
#pragma unroll
    for (int k = 0; k < TK; k++) {
        int r = g_yrow[k];
        float w = g_w[r];
        float4 v = __ldg(&neu4[(size_t)r * NV4 + c4]);
        my.x = fmaf(w, v.x, my.x); my.y = fmaf(w, v.y, my.y);
        my.z = fmaf(w, v.z, my.z); my.w = fmaf(w, v.w, my.w);
    }
    reinterpret_cast<float4*>(g_mix_y)[c4] = my;

    float4 mz = {0,0,0,0};
#pragma unroll
    for (int k = 0; k < ZTK; k++) {
        int r = g_zrow[k];
        float w = g_w[r];
        float4 v = __ldg(&neu4[(size_t)r * NV4 + c4]);
        mz.x = fmaf(w, v.x, mz.x); mz.y = fmaf(w, v.y, mz.y);
        mz.z = fmaf(w, v.z, mz.z); mz.w = fmaf(w, v.w, mz.w);
    }
    reinterpret_cast<float4*>(g_mix_z)[c4] = mz;
}

// ---------------- K7a: update x rows 0..XS-2 (4 rows/block, float4) ----------------
__global__ void k_updx(const float* __restrict__ ages, float* __restrict__ out_neu) {
    int t = threadIdx.x;
    int r0 = blockIdx.x * 4;
    float invdx = g_inv_dx;
    const float4* ip  = reinterpret_cast<const float4*>(g_inpt);
    const float4* mxp = reinterpret_cast<const float4*>(g_mix_x);
    for (int rr = 0; rr < 4; rr++) {
        int r = r0 + rr;
        if (r >= XS - 1) break;   // uniform across block
        float s = g_resp[r] * invdx / __ldg(&ages[r]);
        float4 v[7];
        float ssq = 0.0f;
#pragma unroll
        for (int j = 0; j < 7; j++) {
            int c4 = t + j * 256;
            if (c4 < NV4) {
                float4 iv = ip[c4], mv = mxp[c4];
                float4 vv;
                vv.x = fmaf(s, iv.x, mv.x);
                vv.y = fmaf(s, iv.y, mv.y);
                vv.z = fmaf(s, iv.z, mv.z);
                vv.w = fmaf(s, iv.w, mv.w);
                v[j] = vv;
                ssq = fmaf(vv.x, vv.x, ssq);
                ssq = fmaf(vv.y, vv.y, ssq);
                ssq = fmaf(vv.z, vv.z, ssq);
                ssq = fmaf(vv.w, vv.w, ssq);
            }
        }
        float tot = blockReduceSumB(ssq);
        float inv = 1.0f / (sqrtf(tot) + 1e-12f);
        float4* dst = reinterpret_cast<float4*>(out_neu) + (size_t)r * NV4;
#pragma unroll
        for (int j = 0; j < 7; j++) {
            int c4 = t + j * 256;
            if (c4 < NV4) {
                float4 o = v[j];
                o.x *= inv; o.y *= inv; o.z *= inv; o.w *= inv;
                __stcs(dst + c4, o);
            }
        }
    }
}

// ---------------- K7b: update 16 y rows + 8 z rows (float4) ----------------
__global__ void k_updyz(const float* __restrict__ ages, float* __restrict__ out_neu) {
    int b = blockIdx.x;
    int t = threadIdx.x;
    int r; float val; const float4* mix;
    if (b < TK) { r = g_yrow[b]; val = g_yval[b]; mix = reinterpret_cast<const float4*>(g_mix_y); }
    else        { r = g_zrow[b - TK]; val = g_zval[b - TK]; mix = reinterpret_cast<const float4*>(g_mix_z); }
    float s = val / __ldg(&ages[r]);
    const float4* ip = reinterpret_cast<const float4*>(g_inpt);
    float4 v[7];
    float ssq = 0.0f;
#pragma unroll
    for (int j = 0; j < 7; j++) {
        int c4 = t + j * 256;
        if (c4 < NV4) {
            float4 iv = ip[c4], mv = mix[c4];
            float4 vv;
            vv.x = fmaf(s, iv.x, mv.x);
            vv.y = fmaf(s, iv.y, mv.y);
            vv.z = fmaf(s, iv.z, mv.z);
            vv.w = fmaf(s, iv.w, mv.w);
            v[j] = vv;
            ssq = fmaf(vv.x, vv.x, ssq);
            ssq = fmaf(vv.y, vv.y, ssq);
            ssq = fmaf(vv.z, vv.z, ssq);
            ssq = fmaf(vv.w, vv.w, ssq);
        }
    }
    float tot = blockReduceSumB(ssq);
    float inv = 1.0f / (sqrtf(tot) + 1e-12f);
    float4* dst = reinterpret_cast<float4*>(out_neu) + (size_t)r * NV4;
#pragma unroll
    for (int j = 0; j < 7; j++) {
        int c4 = t + j * 256;
        if (c4 < NV4) {
            float4 o = v[j];
            o.x *= inv; o.y *= inv; o.z *= inv; o.w *= inv;
            __stcs(dst + c4, o);
        }
    }
}

// ---------------- launch ----------------
extern "C" void kernel_launch(void* const* d_in, const int* in_sizes, int n_in,
                              void* d_out, int out_size) {
    (void)in_sizes; (void)n_in; (void)out_size;
    const float* x       = (const float*)d_in[0];
    const float* z       = (const float*)d_in[1];
    const float* yresp   = (const float*)d_in[2];
    const float* neurons = (const float*)d_in[3];
    const float* ages    = (const float*)d_in[4];

    float* out       = (float*)d_out;
    float* out_z     = out;                                // 64
    float* out_final = out + ZS;                           // 6208
    float* out_neu   = out + ZS + DD;                      // 6208*6208
    float* out_ages  = out + ZS + DD + (size_t)DD * DD;    // 6208

    k_init<<<(DD + 255) / 256, 256>>>(x, z, yresp, ages, out_z, out_final, out_ages);
    k_main<<<MIXBLK + DD, 256>>>((const float4*)neurons, out_neu);
    k_ycand<<<32, 32>>>();
    k_final<<<1, 1024>>>(ages, out_z, out_final, out_ages);
    k_mixyz<<<(NV4 + 255) / 256, 256>>>((const float4*)neurons);
    k_updx<<<(XS - 1 + 3) / 4, 256>>>(ages, out_neu);
    k_updyz<<<TK + ZTK, 256>>>(ages, out_neu);
}